// round 4
// baseline (speedup 1.0000x reference)
#include <cuda_runtime.h>
#include <math.h>

#define THREADS 256

// Exact sliding-window recurrence for the truncated biexponential FIR.
// out[b,i] = sum_{j=0..Kt-1} kernel[j] * u[b, i+Kt-1-j]
// kernel[j] = (r1^(j+1) - r2^(j+1)) / scale
// A[i] = sum_j r1^(j+1) u[i+Kt-1-j]  obeys  A[i] = r1*(A[i-1] + u_new - r1^Kt * u_old)
__global__ void biexp_iir_kernel(const float* __restrict__ u,
                                 float* __restrict__ out,
                                 int T_IN, int T_OUT, int Kt, int chunk,
                                 float r1, float r2, float d1, float d2,
                                 float inv_scale)
{
    extern __shared__ float smem[];
    float* su = smem;                         // staged input row (T_IN floats)
    float* so = smem + ((T_IN + 4) & ~3);     // staged output row (16B aligned)

    const int row = blockIdx.x;
    const float* urow = u + (size_t)row * T_IN;
    float* orow = out + (size_t)row * T_OUT;
    const int tid = threadIdx.x;

    // ---- Phase 1: coalesced float4 load of the input row into SMEM ----
    {
        const int n4 = T_IN >> 2;
        const float4* u4 = (const float4*)urow;   // row base is 16B aligned (T_IN*4 % 16 == 0 here; guarded by remainder loop anyway)
        float4* s4 = (float4*)su;
        for (int i = tid; i < n4; i += THREADS) s4[i] = u4[i];
        for (int i = (n4 << 2) + tid; i < T_IN; i += THREADS) su[i] = urow[i];
    }
    __syncthreads();

    // ---- Phase 2: per-thread warm-up + recurrence over its segment ----
    const int o0 = tid * chunk;               // chunk is odd -> LDS stride is bank-conflict-free
    if (o0 < T_OUT) {
        const int n = min(chunk, T_OUT - o0);
        const float* p = su + o0;

        // Warm-up (Horner): A = sum_{m=0..Kt-1} r1^(Kt-1-m) * p[m], then *r1
        float A = 0.0f, Bv = 0.0f;
        #pragma unroll 4
        for (int m = 0; m < Kt; ++m) {
            const float x = p[m];
            A  = fmaf(r1, A,  x);
            Bv = fmaf(r2, Bv, x);
        }
        A *= r1;
        Bv *= r2;
        so[o0] = (A - Bv) * inv_scale;

        // Sliding recurrence for the remaining outputs of this segment
        for (int i = 1; i < n; ++i) {
            const float un = p[Kt - 1 + i];
            const float uo = p[i - 1];
            const float t1 = fmaf(-d1, uo, un);   // u_new - r1^Kt * u_old
            const float t2 = fmaf(-d2, uo, un);   // u_new - r2^Kt * u_old (~un; d2 ~ 2e-16)
            A  = fmaf(r1, A,  r1 * t1);
            Bv = fmaf(r2, Bv, r2 * t2);
            so[o0 + i] = (A - Bv) * inv_scale;
        }
    }
    __syncthreads();

    // ---- Phase 3: coalesced float4 store of the output row ----
    {
        const int n4 = T_OUT >> 2;
        float4* so4 = (float4*)so;
        float4* or4 = (float4*)orow;
        for (int i = tid; i < n4; i += THREADS) or4[i] = so4[i];
        for (int i = (n4 << 2) + tid; i < T_OUT; i += THREADS) orow[i] = so[i];
    }
}

extern "C" void kernel_launch(void* const* d_in, const int* in_sizes, int n_in,
                              void* d_out, int out_size)
{
    const float* u = (const float*)d_in[0];

    // Derive shapes generically from sizes:
    //   in_sizes[0] = B*T_IN, in_sizes[1] = Kt, out_size = B*T_OUT, T_IN = T_OUT + Kt - 1
    const int Kt = in_sizes[1];
    const int B = (in_sizes[0] - out_size) / (Kt - 1);
    const int T_OUT = out_size / B;
    const int T_IN = T_OUT + Kt - 1;

    // Analytic biexponential constants (double precision on host)
    const double TAU1 = 30.0, TAU2 = 5.0;
    const double r1d = exp(-1.0 / TAU1);
    const double r2d = exp(-1.0 / TAU2);
    const double r = TAU1 / TAU2, dd = TAU1 - TAU2;
    const double scale = pow(r, -TAU2 / dd) - pow(r, -TAU1 / dd);

    const float r1 = (float)r1d;
    const float r2 = (float)r2d;
    const float d1 = (float)pow(r1d, (double)Kt);
    const float d2 = (float)pow(r2d, (double)Kt);
    const float inv_scale = (float)(1.0 / scale);

    // Per-thread segment length; forced odd for conflict-free SMEM access.
    int chunk = (T_OUT + THREADS - 1) / THREADS;
    if ((chunk & 1) == 0) chunk++;

    const int smem_bytes = (((T_IN + 4) & ~3) + T_OUT) * (int)sizeof(float);
    cudaFuncSetAttribute(biexp_iir_kernel,
                         cudaFuncAttributeMaxDynamicSharedMemorySize, smem_bytes);

    biexp_iir_kernel<<<B, THREADS, smem_bytes>>>(
        u, (float*)d_out, T_IN, T_OUT, Kt, chunk, r1, r2, d1, d2, inv_scale);
}

// round 5
// speedup vs baseline: 1.5734x; 1.5734x over previous
#include <cuda_runtime.h>
#include <math.h>

#define THREADS 256
#define HALVES  2

// Exact sliding-window recurrence for the truncated biexponential FIR.
//   out[i] = sum_{j=0..Kt-1} kernel[j] * u[i+Kt-1-j],  kernel[j]=(r1^(j+1)-r2^(j+1))/scale
// State Abar = scale^-1 * sum_j r1^(j+1) u[i+Kt-1-j] obeys
//   Abar_i = r1*Abar_{i-1} + c1*u_new + e1*u_old   (c1=r1/scale, e1=-r1^(Kt+1)/scale)
// The r2 chain's u_old term (r2^(Kt+1) ~ 1.9e-16) is exactly 0 in fp32 and dropped.
__global__ __launch_bounds__(THREADS, 2)
void biexp_iir_kernel(const float* __restrict__ u,
                      float* __restrict__ out,
                      int T_IN, int T_BLK, int Kt, int kb_start, int chunk,
                      float r1, float r2, float c1, float e1, float c2)
{
    extern __shared__ float smem[];
    const int T_BIN = T_BLK + Kt - 1;               // staged input length per block
    float* su = smem;                               // input slice
    float* so = smem + T_BIN;                       // output slice (T_BIN mult of 4 -> aligned)

    const int row  = blockIdx.x / HALVES;
    const int half = blockIdx.x % HALVES;
    const float* urow = u + (size_t)row * T_IN + (size_t)half * T_BLK;
    float* orow = out + (size_t)row * (HALVES * T_BLK) + (size_t)half * T_BLK;
    const int tid = threadIdx.x;

    // ---- Phase 1: coalesced, deeply-MLP'd float4 load of the input slice ----
    {
        const int n4 = T_BIN >> 2;                  // T_BIN = 10180 -> 2545
        const float4* u4 = (const float4*)urow;     // 16B aligned: (T_IN and T_BLK) % 4 == 0
        float4* s4 = (float4*)su;
        float4 r[10];
        #pragma unroll
        for (int k = 0; k < 10; ++k) {
            int i = tid + k * THREADS;
            if (i < n4) r[k] = u4[i];
        }
        #pragma unroll
        for (int k = 0; k < 10; ++k) {
            int i = tid + k * THREADS;
            if (i < n4) s4[i] = r[k];
        }
    }
    __syncthreads();

    // ---- Phase 2: per-thread warm-up + sliding recurrence ----
    const int o0 = tid * chunk;                     // chunk odd -> conflict-free LDS/STS
    if (o0 < T_BLK) {
        const int n = min(chunk, T_BLK - o0);
        const float* p = su + o0;

        // Warm-up. Slow chain (r1) needs all Kt taps; fast chain (r2) only the
        // last Kt-kb_start taps (r2^65 ~ 2e-6: below output noise floor).
        float A = 0.0f, Bv = 0.0f;
        int m = 0;
        #pragma unroll 4
        for (; m < kb_start; ++m) A = fmaf(r1, A, p[m]);
        #pragma unroll 4
        for (; m < Kt; ++m) {
            const float x = p[m];
            A  = fmaf(r1, A, x);
            Bv = fmaf(r2, Bv, x);
        }
        A *= c1;                                    // fold r1 * inv_scale
        Bv *= c2;                                   // fold r2 * inv_scale
        so[o0] = A - Bv;

        #pragma unroll 4
        for (int i = 1; i < n; ++i) {
            const float un = p[Kt - 1 + i];
            const float uo = p[i - 1];
            A  = fmaf(r1, A, fmaf(e1, uo, c1 * un));
            Bv = fmaf(r2, Bv, c2 * un);
            so[o0 + i] = A - Bv;
        }
    }
    __syncthreads();

    // ---- Phase 3: coalesced, MLP'd float4 store of the output slice ----
    {
        const int n4 = T_BLK >> 2;                  // 2500
        float4* so4 = (float4*)so;
        float4* or4 = (float4*)orow;
        float4 r[10];
        #pragma unroll
        for (int k = 0; k < 10; ++k) {
            int i = tid + k * THREADS;
            if (i < n4) r[k] = so4[i];
        }
        #pragma unroll
        for (int k = 0; k < 10; ++k) {
            int i = tid + k * THREADS;
            if (i < n4) or4[i] = r[k];
        }
    }
}

extern "C" void kernel_launch(void* const* d_in, const int* in_sizes, int n_in,
                              void* d_out, int out_size)
{
    const float* u = (const float*)d_in[0];

    // Shapes: in_sizes[0] = B*T_IN, in_sizes[1] = Kt, out_size = B*T_OUT
    const int Kt = in_sizes[1];                     // 181
    const int B = (in_sizes[0] - out_size) / (Kt - 1);
    const int T_OUT = out_size / B;                 // 20000
    const int T_IN = T_OUT + Kt - 1;                // 20180
    const int T_BLK = T_OUT / HALVES;               // 10000
    const int T_BIN = T_BLK + Kt - 1;               // 10180

    // Analytic constants (double precision on host)
    const double TAU1 = 30.0, TAU2 = 5.0;
    const double r1d = exp(-1.0 / TAU1);
    const double r2d = exp(-1.0 / TAU2);
    const double rr = TAU1 / TAU2, dd = TAU1 - TAU2;
    const double scale = pow(rr, -TAU2 / dd) - pow(rr, -TAU1 / dd);
    const double s = 1.0 / scale;

    const float r1 = (float)r1d;
    const float r2 = (float)r2d;
    const float c1 = (float)(r1d * s);
    const float e1 = (float)(-pow(r1d, (double)(Kt + 1)) * s);
    const float c2 = (float)(r2d * s);

    // Fast chain warm-up truncation: keep last ~64 taps.
    int kb_start = Kt - 64;
    if (kb_start < 0) kb_start = 0;

    // Per-thread segment; odd for conflict-free SMEM.
    int chunk = (T_BLK + THREADS - 1) / THREADS;    // 40
    if ((chunk & 1) == 0) chunk++;                  // 41

    const int so_len = THREADS * chunk;             // covers all o0+i
    const int smem_bytes = (T_BIN + so_len) * (int)sizeof(float);
    cudaFuncSetAttribute(biexp_iir_kernel,
                         cudaFuncAttributeMaxDynamicSharedMemorySize, smem_bytes);

    biexp_iir_kernel<<<B * HALVES, THREADS, smem_bytes>>>(
        u, (float*)d_out, T_IN, T_BLK, Kt, kb_start, chunk,
        r1, r2, c1, e1, c2);
}

// round 7
// speedup vs baseline: 1.8841x; 1.1975x over previous
#include <cuda_runtime.h>
#include <math.h>

#define THREADS 256
#define HALVES  2

__device__ __forceinline__ unsigned smem_u32(const void* p) {
    return (unsigned)__cvta_generic_to_shared(p);
}

// Exact sliding-window recurrence for the truncated biexponential FIR.
//   out[i] = sum_{j=0..Kt-1} kernel[j]*u[i+Kt-1-j], kernel[j]=(r1^(j+1)-r2^(j+1))/scale
// Scaled state S_i = sum_j (r1^(j+1)/scale) u[i+Kt-1-j] obeys
//   S_i = r1*S_{i-1} + c1*u[i+Kt-1] + e1*u[i-1]   (c1=r1/scale, e1=-r1^(Kt+1)/scale)
// The r2 chain's u_old coefficient (r2^(Kt+1) ~ 1.9e-16) is exactly 0 in fp32.
__global__ __launch_bounds__(THREADS, 2)
void biexp_iir_kernel(const float* __restrict__ u,
                      float* __restrict__ out,
                      int T_IN, int T_BLK, int Km1, int WG, int BG0, int chunk,
                      float r1, float r2, float r14, float r24,
                      float c1, float e1, float c2)
{
    extern __shared__ float smem[];
    float* su = smem + 4;               // 4-float zero pad lives at smem[0..3]
    const int T_BIN = T_BLK + Km1;      // 10180
    float* so = su + T_BIN;             // (4 + 10180) words -> 16B aligned

    const int row  = blockIdx.x / HALVES;
    const int half = blockIdx.x % HALVES;
    const float* urow = u + (size_t)row * T_IN + (size_t)half * T_BLK;
    float* orow = out + (size_t)row * (HALVES * T_BLK) + (size_t)half * T_BLK;
    const int tid = threadIdx.x;

    // ---- Phase 1: cp.async bulk copy of the input slice into SMEM ----
    {
        const float4* g4 = (const float4*)urow;   // 16B aligned (T_IN, T_BLK mult of 4)
        const int n4 = T_BIN >> 2;                // 2545, no tail
        unsigned sb = smem_u32(su);
        for (int i = tid; i < n4; i += THREADS) {
            asm volatile("cp.async.cg.shared.global [%0], [%1], 16;"
                         :: "r"(sb + i * 16), "l"(g4 + i));
        }
        asm volatile("cp.async.commit_group;");
        if (tid < 4) smem[tid] = 0.0f;            // zero pad: p[-1] for thread 0
        asm volatile("cp.async.wait_group 0;");
    }
    __syncthreads();

    // ---- Phase 2: vectorized warm-up + sliding recurrence ----
    const int o0 = tid * chunk;                   // chunk ≡ 4 (mod 8): conflict-free f4
    if (o0 < T_BLK) {
        const int n = min(chunk, T_BLK - o0);     // multiple of 4 by construction
        const float* p = su + o0;
        const float4* p4 = (const float4*)p;

        // Warm-up: H = sum_{m=0..Km1-1} r1^(Km1-1-m) p[m] via 4 split Horner
        // chains (ratio r1^4); fast chain keeps only the last 64 taps.
        float A0 = 0.f, A1 = 0.f, A2 = 0.f, A3 = 0.f;
        float B0 = 0.f, B1 = 0.f, B2 = 0.f, B3 = 0.f;
        int g = 0;
        #pragma unroll 4
        for (; g < BG0; ++g) {
            const float4 x = p4[g];
            A0 = fmaf(r14, A0, x.x); A1 = fmaf(r14, A1, x.y);
            A2 = fmaf(r14, A2, x.z); A3 = fmaf(r14, A3, x.w);
        }
        #pragma unroll 4
        for (; g < WG; ++g) {
            const float4 x = p4[g];
            A0 = fmaf(r14, A0, x.x); A1 = fmaf(r14, A1, x.y);
            A2 = fmaf(r14, A2, x.z); A3 = fmaf(r14, A3, x.w);
            B0 = fmaf(r24, B0, x.x); B1 = fmaf(r24, B1, x.y);
            B2 = fmaf(r24, B2, x.z); B3 = fmaf(r24, B3, x.w);
        }
        const float H  = fmaf(fmaf(fmaf(A0, r1, A1), r1, A2), r1, A3);
        const float HB = fmaf(fmaf(fmaf(B0, r2, B1), r2, B2), r2, B3);
        float S  = c1 * H;      // S_{-1}  (taps p[-1..Km1-1], p[-1]=0 via pad)
        float SB = c2 * HB;

        // Sliding recurrence, 4 outputs per iteration.
        float prev = p[-1];                       // pad (tid 0) or neighbor value
        const float4* pn4 = (const float4*)(p + Km1);
        float4* so4 = (float4*)(so + o0);
        const int q4 = n >> 2;
        #pragma unroll 2
        for (int q = 0; q < q4; ++q) {
            const float4 un = pn4[q];
            const float4 cu = p4[q];
            float4 o;
            S = fmaf(r1, S, fmaf(e1, prev, c1 * un.x));
            SB = fmaf(r2, SB, c2 * un.x);  o.x = S - SB;
            S = fmaf(r1, S, fmaf(e1, cu.x, c1 * un.y));
            SB = fmaf(r2, SB, c2 * un.y);  o.y = S - SB;
            S = fmaf(r1, S, fmaf(e1, cu.y, c1 * un.z));
            SB = fmaf(r2, SB, c2 * un.z);  o.z = S - SB;
            S = fmaf(r1, S, fmaf(e1, cu.z, c1 * un.w));
            SB = fmaf(r2, SB, c2 * un.w);  o.w = S - SB;
            prev = cu.w;
            so4[q] = o;
        }
    }
    __syncthreads();

    // ---- Phase 3: coalesced, MLP'd float4 store of the output slice ----
    {
        const int n4 = T_BLK >> 2;                // 2500
        const float4* so4 = (const float4*)so;
        float4* or4 = (float4*)orow;
        float4 r[10];
        #pragma unroll
        for (int k = 0; k < 10; ++k) {
            int i = tid + k * THREADS;
            if (i < n4) r[k] = so4[i];
        }
        #pragma unroll
        for (int k = 0; k < 10; ++k) {
            int i = tid + k * THREADS;
            if (i < n4) or4[i] = r[k];
        }
    }
}

extern "C" void kernel_launch(void* const* d_in, const int* in_sizes, int n_in,
                              void* d_out, int out_size)
{
    const float* u = (const float*)d_in[0];

    // Shapes: in_sizes[0] = B*T_IN, in_sizes[1] = Kt, out_size = B*T_OUT
    const int Kt = in_sizes[1];                   // 181
    const int B = (in_sizes[0] - out_size) / (Kt - 1);
    const int T_OUT = out_size / B;               // 20000
    const int T_IN = T_OUT + Kt - 1;              // 20180
    const int T_BLK = T_OUT / HALVES;             // 10000
    const int Km1 = Kt - 1;                       // 180 (multiple of 4)
    const int T_BIN = T_BLK + Km1;                // 10180

    // Analytic constants (double precision on host)
    const double TAU1 = 30.0, TAU2 = 5.0;
    const double r1d = exp(-1.0 / TAU1);
    const double r2d = exp(-1.0 / TAU2);
    const double rr = TAU1 / TAU2, dd = TAU1 - TAU2;
    const double scale = pow(rr, -TAU2 / dd) - pow(rr, -TAU1 / dd);
    const double s = 1.0 / scale;

    const float r1 = (float)r1d;
    const float r2 = (float)r2d;
    const float r14 = (float)pow(r1d, 4.0);
    const float r24 = (float)pow(r2d, 4.0);
    const float c1 = (float)(r1d * s);
    const float e1 = (float)(-pow(r1d, (double)(Kt + 1)) * s);
    const float c2 = (float)(r2d * s);

    // Warm-up groups; fast chain keeps the last 16 groups (64 taps).
    const int WG = Km1 / 4;                       // 45
    int BG0 = WG - 16; if (BG0 < 0) BG0 = 0;      // 29

    // Per-thread segment: multiple of 4, and (chunk/4) odd for conflict-free
    // 128-bit shared access (stride ≡ 4 mod 8 words-of-4).
    int chunk = (T_BLK + THREADS - 1) / THREADS;  // 40
    chunk = (chunk + 3) & ~3;
    if ((chunk & 7) == 0) chunk += 4;             // 44

    const int nt = (T_BLK + chunk - 1) / chunk;   // 228 active threads
    const int so_len = nt * chunk;                // 10032
    const int smem_bytes = (4 + T_BIN + so_len) * (int)sizeof(float);
    cudaFuncSetAttribute(biexp_iir_kernel,
                         cudaFuncAttributeMaxDynamicSharedMemorySize, smem_bytes);

    biexp_iir_kernel<<<B * HALVES, THREADS, smem_bytes>>>(
        u, (float*)d_out, T_IN, T_BLK, Km1, WG, BG0, chunk,
        r1, r2, r14, r24, c1, e1, c2);
}

// round 8
// speedup vs baseline: 1.9680x; 1.0445x over previous
#include <cuda_runtime.h>
#include <math.h>

#define THREADS 288
#define HALVES  2
#define CHUNK   36      // per-thread outputs; 36 % 8 == 4 -> conflict-free LDS.128
#define NGRP    9       // CHUNK / 4
#define KM1     180     // Kt - 1 == 5 * CHUNK
#define WIN     5       // KM1 / CHUNK

// Exact sliding-window recurrence for the truncated biexponential FIR.
//   out[i] = sum_{j=0..Kt-1} kernel[j]*u[i+Kt-1-j], kernel[j]=(r1^(j+1)-r2^(j+1))/scale
// Scaled state S_i = (1/scale) sum_j r1^(j+1) u[i+Kt-1-j] obeys
//   S_i = r1*S_{i-1} + c1*u[i+Kt-1] + e1*u[i-1]  (c1=r1/scale, e1=-r1^(Kt+1)/scale)
// Initial state S_{-1} is assembled EXACTLY (incl. the u[o0-1] tap -- the R7 bug)
// from 36-wide local sums L_k shared across threads via smem.
__global__ __launch_bounds__(THREADS, 2)
void biexp_scan_kernel(const float* __restrict__ u, float* __restrict__ out,
                       int T_IN, int T_BLK, int nt, int nL,
                       float r1, float r2, float r14, float r24,
                       float c1, float e1, float c2,
                       float w10, float w11, float w12, float w13, float w14,
                       float w1p,
                       float w20, float w21, float w22, float w23, float w24)
{
    extern __shared__ float smem[];
    float* su = smem + 4;                      // smem[0..3] = zero pad (p[-1] of tid 0)
    const int T_BIN = T_BLK + KM1;             // 10180
    float* so = su + T_BIN;                    // word 10184 -> 16B aligned
    float* LA = so + nt * CHUNK;               // local sums, slow chain
    float* LB = LA + nL;                       // local sums, fast chain

    const int row  = blockIdx.x / HALVES;
    const int half = blockIdx.x % HALVES;
    const float* urow = u + (size_t)row * T_IN + (size_t)half * T_BLK;
    float* orow = out + (size_t)row * (HALVES * T_BLK) + (size_t)half * T_BLK;
    const int tid = threadIdx.x;

    // ---- Phase 1: cp.async stage of the input slice ----
    {
        const float4* g4 = (const float4*)urow;   // 16B aligned (T_IN, T_BLK mult of 4)
        const int n4 = T_BIN >> 2;                // 2545
        unsigned sb = (unsigned)__cvta_generic_to_shared(su);
        for (int i = tid; i < n4; i += THREADS)
            asm volatile("cp.async.cg.shared.global [%0], [%1], 16;"
                         :: "r"(sb + i * 16), "l"(g4 + i));
        asm volatile("cp.async.commit_group;");
        if (tid < 4) smem[tid] = 0.0f;
        asm volatile("cp.async.wait_group 0;");
    }
    __syncthreads();

    // ---- Phase 2a: local weighted sums over each 36-chunk ----
    // L_k = sum_{m=0..35} r^(35-m) * su[36k+m]  (4-way split Horner, ratio r^4)
    if (tid < nL) {
        const float4* q4 = (const float4*)(su + tid * CHUNK);
        float A0=0.f,A1=0.f,A2=0.f,A3=0.f,B0=0.f,B1=0.f,B2=0.f,B3=0.f;
        #pragma unroll
        for (int g = 0; g < NGRP; ++g) {
            const float4 x = q4[g];
            A0=fmaf(r14,A0,x.x); A1=fmaf(r14,A1,x.y);
            A2=fmaf(r14,A2,x.z); A3=fmaf(r14,A3,x.w);
            B0=fmaf(r24,B0,x.x); B1=fmaf(r24,B1,x.y);
            B2=fmaf(r24,B2,x.z); B3=fmaf(r24,B3,x.w);
        }
        LA[tid] = fmaf(fmaf(fmaf(A0,r1,A1),r1,A2),r1,A3);
        LB[tid] = fmaf(fmaf(fmaf(B0,r2,B1),r2,B2),r2,B3);
    }
    __syncthreads();

    // ---- Phase 2b: assemble exact initial state, run recurrence ----
    const int o0 = tid * CHUNK;
    if (o0 < T_BLK) {
        const int n = min(CHUNK, T_BLK - o0);
        float prev = su[o0 - 1];               // tid 0 hits the zero pad

        float S = w1p * prev;                  // the previously-missing p[-1] tap
        S = fmaf(w10, LA[tid],     S);
        S = fmaf(w11, LA[tid + 1], S);
        S = fmaf(w12, LA[tid + 2], S);
        S = fmaf(w13, LA[tid + 3], S);
        S = fmaf(w14, LA[tid + 4], S);
        float SB =     w20 * LB[tid];
        SB = fmaf(w21, LB[tid + 1], SB);
        SB = fmaf(w22, LB[tid + 2], SB);
        SB = fmaf(w23, LB[tid + 3], SB);
        SB = fmaf(w24, LB[tid + 4], SB);

        const float4* cu4 = (const float4*)(su + o0);
        const float4* un4 = (const float4*)(su + o0 + KM1);
        float4* so4 = (float4*)(so + o0);
        const int q4n = n >> 2;

        #define STEP(UN, UO) do { \
            S  = fmaf(r1, S, fmaf(e1, (UO), c1 * (UN))); \
            SB = fmaf(r2, SB, c2 * (UN)); } while (0)
        #define BODY(q) do { \
            const float4 un = un4[q]; \
            const float4 cu = cu4[q]; \
            float4 o; \
            STEP(un.x, prev); o.x = S - SB; \
            STEP(un.y, cu.x); o.y = S - SB; \
            STEP(un.z, cu.y); o.z = S - SB; \
            STEP(un.w, cu.z); o.w = S - SB; \
            prev = cu.w; \
            so4[q] = o; } while (0)

        if (q4n == NGRP) {
            #pragma unroll
            for (int q = 0; q < NGRP; ++q) BODY(q);
        } else {
            for (int q = 0; q < q4n; ++q) BODY(q);
        }
        #undef BODY
        #undef STEP
    }
    __syncthreads();

    // ---- Phase 3: coalesced MLP'd float4 store of the output slice ----
    {
        const int n4 = T_BLK >> 2;             // 2500
        const float4* s4 = (const float4*)so;
        float4* g4 = (float4*)orow;
        float4 r[9];
        #pragma unroll
        for (int k = 0; k < 9; ++k) {
            int i = tid + k * THREADS;
            if (i < n4) r[k] = s4[i];
        }
        #pragma unroll
        for (int k = 0; k < 9; ++k) {
            int i = tid + k * THREADS;
            if (i < n4) g4[i] = r[k];
        }
    }
}

extern "C" void kernel_launch(void* const* d_in, const int* in_sizes, int n_in,
                              void* d_out, int out_size)
{
    const float* u = (const float*)d_in[0];

    // Shapes: in_sizes[0] = B*T_IN, in_sizes[1] = Kt, out_size = B*T_OUT
    const int Kt = in_sizes[1];                // 181
    const int B = (in_sizes[0] - out_size) / (Kt - 1);
    const int T_OUT = out_size / B;            // 20000
    const int T_IN = T_OUT + Kt - 1;           // 20180
    const int T_BLK = T_OUT / HALVES;          // 10000
    const int T_BIN = T_BLK + KM1;             // 10180

    // Analytic constants (double precision on host)
    const double TAU1 = 30.0, TAU2 = 5.0;
    const double r1d = exp(-1.0 / TAU1);
    const double r2d = exp(-1.0 / TAU2);
    const double rr = TAU1 / TAU2, dd = TAU1 - TAU2;
    const double scale = pow(rr, -TAU2 / dd) - pow(rr, -TAU1 / dd);
    const double s = 1.0 / scale;

    const float r1  = (float)r1d;
    const float r2  = (float)r2d;
    const float r14 = (float)pow(r1d, 4.0);
    const float r24 = (float)pow(r2d, 4.0);
    const float c1  = (float)(r1d * s);
    const float e1  = (float)(-pow(r1d, (double)(Kt + 1)) * s);
    const float c2  = (float)(r2d * s);

    // State-assembly weights: S_{-1} = c1*( r1^180 * u[o0-1] + sum_c r1^(144-36c) L_{t+c} )
    const float w10 = (float)(r1d * s * pow(r1d, 144.0));
    const float w11 = (float)(r1d * s * pow(r1d, 108.0));
    const float w12 = (float)(r1d * s * pow(r1d, 72.0));
    const float w13 = (float)(r1d * s * pow(r1d, 36.0));
    const float w14 = (float)(r1d * s);
    const float w1p = (float)(r1d * s * pow(r1d, 180.0));
    const float w20 = (float)(r2d * s * pow(r2d, 144.0));
    const float w21 = (float)(r2d * s * pow(r2d, 108.0));
    const float w22 = (float)(r2d * s * pow(r2d, 72.0));
    const float w23 = (float)(r2d * s * pow(r2d, 36.0));
    const float w24 = (float)(r2d * s);

    const int nt = (T_BLK + CHUNK - 1) / CHUNK;   // 278 output threads
    const int nL = nt + WIN - 1;                  // 282 local sums

    const int smem_bytes = (4 + T_BIN + nt * CHUNK + 2 * nL) * (int)sizeof(float);
    cudaFuncSetAttribute(biexp_scan_kernel,
                         cudaFuncAttributeMaxDynamicSharedMemorySize, smem_bytes);

    biexp_scan_kernel<<<B * HALVES, THREADS, smem_bytes>>>(
        u, (float*)d_out, T_IN, T_BLK, nt, nL,
        r1, r2, r14, r24, c1, e1, c2,
        w10, w11, w12, w13, w14, w1p,
        w20, w21, w22, w23, w24);
}

// round 9
// speedup vs baseline: 2.5836x; 1.3128x over previous
#include <cuda_runtime.h>
#include <math.h>

#define THREADS 288
#define HALVES  4       // slices per row
#define CHUNK   20      // per-thread outputs; 20 % 8 == 4 -> conflict-free LDS.128
#define NGRP    5       // CHUNK / 4
#define KM1     180     // Kt - 1 == 9 * CHUNK
#define WIN     9       // KM1 / CHUNK

struct Wts { float a[WIN]; float b[WIN]; float pA; };

// Exact sliding-window recurrence for the truncated biexponential FIR.
//   out[i] = sum_{j=0..Kt-1} kernel[j]*u[i+Kt-1-j], kernel[j]=(r1^(j+1)-r2^(j+1))/scale
// Scaled state S_i = (1/scale) sum_j r1^(j+1) u[i+Kt-1-j] obeys
//   S_i = r1*S_{i-1} + c1*u[i+Kt-1] + e1*u[i-1]  (c1=r1/scale, e1=-r1^(Kt+1)/scale)
// S_{-1} is assembled EXACTLY (incl. the u[o0-1] tap) from CHUNK-wide local
// sums L_k shared across threads via smem. The r2 chain's u_old coefficient
// (r2^(Kt+1) ~ 1.9e-16) is exactly 0 in fp32 and dropped.
__global__ __launch_bounds__(THREADS, 5)
void biexp_scan_kernel(const float* __restrict__ u, float* __restrict__ out,
                       int T_IN, int T_BLK, int nt, int nL,
                       float r1, float r2, float r14, float r24,
                       float c1, float e1, float c2, Wts W)
{
    extern __shared__ float smem[];
    float* su = smem + 4;                      // smem[0..3] = zero pad (p[-1] of tid 0)
    const int T_BIN = T_BLK + KM1;             // 5180
    float* so = su + T_BIN;                    // 16B aligned (4+5180 words)
    float* LA = so + T_BLK;                    // local sums, slow chain
    float* LB = LA + nL;                       // local sums, fast chain

    const int row  = blockIdx.x / HALVES;
    const int half = blockIdx.x % HALVES;
    const float* urow = u + (size_t)row * T_IN + (size_t)half * T_BLK;
    float* orow = out + (size_t)row * (HALVES * T_BLK) + (size_t)half * T_BLK;
    const int tid = threadIdx.x;

    // ---- Phase 1: cp.async stage of the input slice ----
    {
        const float4* g4 = (const float4*)urow;   // 16B aligned (T_IN, T_BLK mult of 4)
        const int n4 = T_BIN >> 2;                // 1295
        unsigned sb = (unsigned)__cvta_generic_to_shared(su);
        for (int i = tid; i < n4; i += THREADS)
            asm volatile("cp.async.cg.shared.global [%0], [%1], 16;"
                         :: "r"(sb + i * 16), "l"(g4 + i));
        asm volatile("cp.async.commit_group;");
        if (tid < 4) smem[tid] = 0.0f;
        asm volatile("cp.async.wait_group 0;");
    }
    __syncthreads();

    // ---- Phase 2a: local weighted sums over each 20-chunk ----
    // L_k = sum_{m=0..19} r^(19-m) * su[20k+m]  (4-way split Horner, ratio r^4)
    if (tid < nL) {
        const float4* q4 = (const float4*)(su + tid * CHUNK);
        float A0=0.f,A1=0.f,A2=0.f,A3=0.f,B0=0.f,B1=0.f,B2=0.f,B3=0.f;
        #pragma unroll
        for (int g = 0; g < NGRP; ++g) {
            const float4 x = q4[g];
            A0=fmaf(r14,A0,x.x); A1=fmaf(r14,A1,x.y);
            A2=fmaf(r14,A2,x.z); A3=fmaf(r14,A3,x.w);
            B0=fmaf(r24,B0,x.x); B1=fmaf(r24,B1,x.y);
            B2=fmaf(r24,B2,x.z); B3=fmaf(r24,B3,x.w);
        }
        LA[tid] = fmaf(fmaf(fmaf(A0,r1,A1),r1,A2),r1,A3);
        LB[tid] = fmaf(fmaf(fmaf(B0,r2,B1),r2,B2),r2,B3);
    }
    __syncthreads();

    // ---- Phase 2b: assemble exact initial state, run recurrence ----
    if (tid < nt) {                            // nt*CHUNK == T_BLK (exact)
        const int o0 = tid * CHUNK;
        float prev = su[o0 - 1];               // tid 0 hits the zero pad

        float S = W.pA * prev;                 // the p[-1] tap of the slow chain
        float SB = 0.0f;
        #pragma unroll
        for (int c = 0; c < WIN; ++c) {
            S  = fmaf(W.a[c], LA[tid + c], S);
            SB = fmaf(W.b[c], LB[tid + c], SB);
        }

        const float4* cu4 = (const float4*)(su + o0);
        const float4* un4 = (const float4*)(su + o0 + KM1);
        float4* so4 = (float4*)(so + o0);

        #define STEP(UN, UO) do { \
            S  = fmaf(r1, S, fmaf(e1, (UO), c1 * (UN))); \
            SB = fmaf(r2, SB, c2 * (UN)); } while (0)
        #pragma unroll
        for (int q = 0; q < NGRP; ++q) {
            const float4 un = un4[q];
            const float4 cu = cu4[q];
            float4 o;
            STEP(un.x, prev); o.x = S - SB;
            STEP(un.y, cu.x); o.y = S - SB;
            STEP(un.z, cu.y); o.z = S - SB;
            STEP(un.w, cu.z); o.w = S - SB;
            prev = cu.w;
            so4[q] = o;
        }
        #undef STEP
    }
    __syncthreads();

    // ---- Phase 3: coalesced MLP'd float4 store of the output slice ----
    {
        const int n4 = T_BLK >> 2;             // 1250
        const float4* s4 = (const float4*)so;
        float4* g4 = (float4*)orow;
        float4 r[5];
        #pragma unroll
        for (int k = 0; k < 5; ++k) {
            int i = tid + k * THREADS;
            if (i < n4) r[k] = s4[i];
        }
        #pragma unroll
        for (int k = 0; k < 5; ++k) {
            int i = tid + k * THREADS;
            if (i < n4) g4[i] = r[k];
        }
    }
}

extern "C" void kernel_launch(void* const* d_in, const int* in_sizes, int n_in,
                              void* d_out, int out_size)
{
    const float* u = (const float*)d_in[0];

    // Shapes: in_sizes[0] = B*T_IN, in_sizes[1] = Kt, out_size = B*T_OUT
    const int Kt = in_sizes[1];                // 181
    const int B = (in_sizes[0] - out_size) / (Kt - 1);
    const int T_OUT = out_size / B;            // 20000
    const int T_IN = T_OUT + Kt - 1;           // 20180
    const int T_BLK = T_OUT / HALVES;          // 5000
    const int T_BIN = T_BLK + KM1;             // 5180

    // Analytic constants (double precision on host)
    const double TAU1 = 30.0, TAU2 = 5.0;
    const double r1d = exp(-1.0 / TAU1);
    const double r2d = exp(-1.0 / TAU2);
    const double rr = TAU1 / TAU2, dd = TAU1 - TAU2;
    const double scale = pow(rr, -TAU2 / dd) - pow(rr, -TAU1 / dd);
    const double s = 1.0 / scale;

    const float r1  = (float)r1d;
    const float r2  = (float)r2d;
    const float r14 = (float)pow(r1d, 4.0);
    const float r24 = (float)pow(r2d, 4.0);
    const float c1  = (float)(r1d * s);
    const float e1  = (float)(-pow(r1d, (double)(Kt + 1)) * s);
    const float c2  = (float)(r2d * s);

    // State-assembly weights: tap p[20c+m] weight = s*r^(180-20c-m); local sum
    // weight r^(19-m) -> chunk weight = s * r^(161-20c). p[-1]: s*r1^181.
    Wts W;
    for (int c = 0; c < WIN; ++c) {
        W.a[c] = (float)(s * pow(r1d, (double)(161 - 20 * c)));
        W.b[c] = (float)(s * pow(r2d, (double)(161 - 20 * c)));
    }
    W.pA = (float)(s * pow(r1d, 181.0));

    const int nt = T_BLK / CHUNK;              // 250 (exact)
    const int nL = nt + WIN - 1;               // 258 local sums

    const int smem_bytes = (4 + T_BIN + T_BLK + 2 * nL) * (int)sizeof(float);
    cudaFuncSetAttribute(biexp_scan_kernel,
                         cudaFuncAttributeMaxDynamicSharedMemorySize, smem_bytes);

    biexp_scan_kernel<<<B * HALVES, THREADS, smem_bytes>>>(
        u, (float*)d_out, T_IN, T_BLK, nt, nL,
        r1, r2, r14, r24, c1, e1, c2, W);
}